// round 13
// baseline (speedup 1.0000x reference)
#include <cuda_runtime.h>
#include <cuda_bf16.h>
#include <cstdint>

typedef __nv_bfloat16 bf16;
typedef uint8_t fp8;

#define CB 8192
#define CT 30
#define CD 256
#define CL 6
#define INV32 0.03125f

// ---------------- scratch ----------------
__device__ bf16  g_canvas[CB*384];
__device__ bf16  g_t1[CB*512];
__device__ bf16  g_t2b[CB*512];
__device__ bf16  g_cv[CB*256];
__device__ float g_ssall[(size_t)CB*6144];
__device__ bf16  g_xb[(size_t)CB*CT*CD];       // bf16 residual stream
__device__ fp8   g_x28[(size_t)CB*CT*CD];      // modulated (fp8)
__device__ fp8   g_o8[(size_t)CB*CT*CD];       // attention out (fp8)
__device__ bf16  g_qkv[(size_t)CB*CT*768];
__device__ fp8   g_ffh8[(size_t)CB*CT*1024];   // silu(ff1) (fp8)
__device__ bf16  g_xin[CB*320];
__device__ float g_part[64];

__device__ bf16  g_ce_w1[512*384];
__device__ bf16  g_ce_w2[256*512];
__device__ bf16  g_adw[(size_t)6144*256];
__device__ float g_adb[6144];
__device__ fp8   g_inp8[CL*768*256];           // x32-scaled fp8 weights
__device__ fp8   g_outp8[CL*256*256];
__device__ fp8   g_ff18[CL*1024*256];
__device__ fp8   g_ff28[CL*256*1024];
__device__ bf16  g_fw1[512*320];
__device__ bf16  g_fw2[512*512];

// ---------------- asm helpers ----------------
__device__ __forceinline__ void cp16(void* smem, const void* gmem) {
    uint32_t s = (uint32_t)__cvta_generic_to_shared(smem);
    asm volatile("cp.async.cg.shared.global [%0], [%1], 16;\n" :: "r"(s), "l"(gmem));
}
__device__ __forceinline__ void cp_commit() { asm volatile("cp.async.commit_group;\n"); }
template<int N> __device__ __forceinline__ void cp_wait() {
    asm volatile("cp.async.wait_group %0;\n" :: "n"(N));
}
__device__ __forceinline__ void ldsm4(uint32_t& r0, uint32_t& r1, uint32_t& r2, uint32_t& r3,
                                      uint32_t addr) {
    asm volatile("ldmatrix.sync.aligned.m8n8.x4.shared.b16 {%0,%1,%2,%3}, [%4];"
                 : "=r"(r0), "=r"(r1), "=r"(r2), "=r"(r3) : "r"(addr));
}
__device__ __forceinline__ void mma16816(float* d, const uint32_t* a, const uint32_t* b) {
    asm volatile("mma.sync.aligned.m16n8k16.row.col.f32.bf16.bf16.f32 "
                 "{%0,%1,%2,%3}, {%4,%5,%6,%7}, {%8,%9}, {%0,%1,%2,%3};"
                 : "+f"(d[0]), "+f"(d[1]), "+f"(d[2]), "+f"(d[3])
                 : "r"(a[0]), "r"(a[1]), "r"(a[2]), "r"(a[3]), "r"(b[0]), "r"(b[1]));
}
__device__ __forceinline__ void mma16832(float* d, const uint32_t* a, const uint32_t* b) {
    asm volatile("mma.sync.aligned.m16n8k32.row.col.f32.e4m3.e4m3.f32 "
                 "{%0,%1,%2,%3}, {%4,%5,%6,%7}, {%8,%9}, {%0,%1,%2,%3};"
                 : "+f"(d[0]), "+f"(d[1]), "+f"(d[2]), "+f"(d[3])
                 : "r"(a[0]), "r"(a[1]), "r"(a[2]), "r"(a[3]), "r"(b[0]), "r"(b[1]));
}
// pack 2 floats -> 2 e4m3 bytes  ({hi,lo} per PTX operand order)
__device__ __forceinline__ uint16_t cvt2_e4m3(float lo, float hi) {
    uint16_t r;
    asm("cvt.rn.satfinite.e4m3x2.f32 %0, %1, %2;" : "=h"(r) : "f"(hi), "f"(lo));
    return r;
}
__device__ __forceinline__ fp8 cvt1_e4m3(float v) {
    return (fp8)(cvt2_e4m3(v, 0.f) & 0xFF);
}

// ============ bf16 GEMM (BN=128, BK=64): context/adaLN/fm ===================
// EPI: 0 bias->bf16 ; 1 bias+silu->bf16 ; 3 bias->fp32
#define GEMM_SMEM (3 * 32768)

template<int EPI>
__global__ void __launch_bounds__(256)
k_gemm(const bf16* __restrict__ A, const bf16* __restrict__ W,
       const float* __restrict__ bias, bf16* __restrict__ outb,
       float* __restrict__ outf, int M, int N, int K)
{
    extern __shared__ __align__(128) char smem[];
    const uint32_t sbase = (uint32_t)__cvta_generic_to_shared(smem);
    const int tid  = threadIdx.x;
    const int wid  = tid >> 5;
    const int lane = tid & 31;
    const int n0   = blockIdx.x * 128;
    const int m0   = blockIdx.y * 128;
    const int wm   = (wid >> 2) * 64;
    const int wn   = (wid & 3) * 32;

    float acc[4][4][4];
    #pragma unroll
    for (int i = 0; i < 4; i++)
        #pragma unroll
        for (int j = 0; j < 4; j++)
            #pragma unroll
            for (int e = 0; e < 4; e++) acc[i][j][e] = 0.f;

    const int nk = K >> 6;

    auto stage_load = [&](int kt) {
        char* sA = smem + (kt % 3) * 32768;
        char* sB = sA + 16384;
        const bf16* gA = A + (size_t)m0 * K + kt * 64;
        const bf16* gB = W + (size_t)n0 * K + kt * 64;
        #pragma unroll
        for (int i = tid; i < 1024; i += 256) {
            int row = i >> 3, g = i & 7;
            cp16(sA + row * 128 + 16 * (g ^ (row & 7)), gA + (size_t)row * K + g * 8);
        }
        #pragma unroll
        for (int i = tid; i < 1024; i += 256) {
            int row = i >> 3, g = i & 7;
            cp16(sB + row * 128 + 16 * (g ^ (row & 7)), gB + (size_t)row * K + g * 8);
        }
        cp_commit();
    };

    stage_load(0);
    if (nk > 1) stage_load(1);

    const int aRow = (lane & 7) + (((lane >> 3) & 1) << 3);
    const int bRow = (lane & 7) + (((lane >> 4) & 1) << 3);
    const int l7   = lane & 7;

    for (int kt = 0; kt < nk; kt++) {
        if (kt < nk - 1) cp_wait<1>(); else cp_wait<0>();
        __syncthreads();
        if (kt + 2 < nk) stage_load(kt + 2);

        uint32_t sA = sbase + (uint32_t)(kt % 3) * 32768;
        uint32_t sB = sA + 16384;
        #pragma unroll
        for (int ks = 0; ks < 4; ks++) {
            uint32_t a[4][4], b[4][2];
            int ca = (ks * 2 + (lane >> 4)) ^ l7;
            int cb = (ks * 2 + ((lane >> 3) & 1)) ^ l7;
            #pragma unroll
            for (int i = 0; i < 4; i++)
                ldsm4(a[i][0], a[i][1], a[i][2], a[i][3],
                      sA + (uint32_t)(wm + i * 16 + aRow) * 128 + ca * 16);
            #pragma unroll
            for (int j2 = 0; j2 < 2; j2++)
                ldsm4(b[j2 * 2][0], b[j2 * 2][1], b[j2 * 2 + 1][0], b[j2 * 2 + 1][1],
                      sB + (uint32_t)(wn + j2 * 16 + bRow) * 128 + cb * 16);
            #pragma unroll
            for (int i = 0; i < 4; i++)
                #pragma unroll
                for (int j = 0; j < 4; j++)
                    mma16816(acc[i][j], a[i], b[j]);
        }
    }

    const int r = lane >> 2;
    const int c = (lane & 3) * 2;
    #pragma unroll
    for (int i = 0; i < 4; i++) {
        #pragma unroll
        for (int j = 0; j < 4; j++) {
            #pragma unroll
            for (int h = 0; h < 2; h++) {
                int m  = m0 + wm + i * 16 + r + h * 8;
                int nn = n0 + wn + j * 8 + c;
                float v0 = acc[i][j][h * 2 + 0] + bias[nn];
                float v1 = acc[i][j][h * 2 + 1] + bias[nn + 1];
                if (EPI == 1) {
                    v0 = v0 / (1.f + __expf(-v0));
                    v1 = v1 / (1.f + __expf(-v1));
                }
                if (EPI == 3) {
                    *(float2*)(outf + (size_t)m * N + nn) = make_float2(v0, v1);
                } else {
                    *(__nv_bfloat162*)(outb + (size_t)m * N + nn) =
                        __nv_bfloat162(__float2bfloat16(v0), __float2bfloat16(v1));
                }
            }
        }
    }
}

// ============ fp8 GEMM (BN=128, BK=128 elems = 128B rows) ===================
// weights pre-scaled x32 -> epilogue scales acc by 1/32.
// EPI: 0 bias->bf16 (qkv) ; 1 bias+silu->fp8 (ff1)
template<int EPI>
__global__ void __launch_bounds__(256)
k_gemm8(const fp8* __restrict__ A, const fp8* __restrict__ W,
        const float* __restrict__ bias, bf16* __restrict__ outb,
        fp8* __restrict__ out8, int M, int N, int K)
{
    extern __shared__ __align__(128) char smem[];
    const uint32_t sbase = (uint32_t)__cvta_generic_to_shared(smem);
    const int tid  = threadIdx.x;
    const int wid  = tid >> 5;
    const int lane = tid & 31;
    const int n0   = blockIdx.x * 128;
    const int m0   = blockIdx.y * 128;
    const int wm   = (wid >> 2) * 64;
    const int wn   = (wid & 3) * 32;

    float acc[4][4][4];
    #pragma unroll
    for (int i = 0; i < 4; i++)
        #pragma unroll
        for (int j = 0; j < 4; j++)
            #pragma unroll
            for (int e = 0; e < 4; e++) acc[i][j][e] = 0.f;

    const int nk = K >> 7;   // BK = 128 fp8

    auto stage_load = [&](int kt) {
        char* sA = smem + (kt % 3) * 32768;
        char* sB = sA + 16384;
        const fp8* gA = A + (size_t)m0 * K + kt * 128;
        const fp8* gB = W + (size_t)n0 * K + kt * 128;
        #pragma unroll
        for (int i = tid; i < 1024; i += 256) {
            int row = i >> 3, g = i & 7;
            cp16(sA + row * 128 + 16 * (g ^ (row & 7)), gA + (size_t)row * K + g * 16);
        }
        #pragma unroll
        for (int i = tid; i < 1024; i += 256) {
            int row = i >> 3, g = i & 7;
            cp16(sB + row * 128 + 16 * (g ^ (row & 7)), gB + (size_t)row * K + g * 16);
        }
        cp_commit();
    };

    stage_load(0);
    if (nk > 1) stage_load(1);

    const int aRow = (lane & 7) + (((lane >> 3) & 1) << 3);
    const int bRow = (lane & 7) + (((lane >> 4) & 1) << 3);
    const int l7   = lane & 7;

    for (int kt = 0; kt < nk; kt++) {
        if (kt < nk - 1) cp_wait<1>(); else cp_wait<0>();
        __syncthreads();
        if (kt + 2 < nk) stage_load(kt + 2);

        uint32_t sA = sbase + (uint32_t)(kt % 3) * 32768;
        uint32_t sB = sA + 16384;
        #pragma unroll
        for (int ks = 0; ks < 4; ks++) {    // each ks = 32 fp8 of K (2 granules)
            uint32_t a[4][4], b[4][2];
            int ca = (ks * 2 + (lane >> 4)) ^ l7;
            int cb = (ks * 2 + ((lane >> 3) & 1)) ^ l7;
            #pragma unroll
            for (int i = 0; i < 4; i++)
                ldsm4(a[i][0], a[i][1], a[i][2], a[i][3],
                      sA + (uint32_t)(wm + i * 16 + aRow) * 128 + ca * 16);
            #pragma unroll
            for (int j2 = 0; j2 < 2; j2++)
                ldsm4(b[j2 * 2][0], b[j2 * 2][1], b[j2 * 2 + 1][0], b[j2 * 2 + 1][1],
                      sB + (uint32_t)(wn + j2 * 16 + bRow) * 128 + cb * 16);
            #pragma unroll
            for (int i = 0; i < 4; i++)
                #pragma unroll
                for (int j = 0; j < 4; j++)
                    mma16832(acc[i][j], a[i], b[j]);
        }
    }

    const int r = lane >> 2;
    const int c = (lane & 3) * 2;
    #pragma unroll
    for (int i = 0; i < 4; i++) {
        #pragma unroll
        for (int j = 0; j < 4; j++) {
            #pragma unroll
            for (int h = 0; h < 2; h++) {
                int m  = m0 + wm + i * 16 + r + h * 8;
                int nn = n0 + wn + j * 8 + c;
                float v0 = acc[i][j][h * 2 + 0] * INV32 + bias[nn];
                float v1 = acc[i][j][h * 2 + 1] * INV32 + bias[nn + 1];
                if (EPI == 1) {
                    v0 = v0 / (1.f + __expf(-v0));
                    v1 = v1 / (1.f + __expf(-v1));
                    *(uint16_t*)(out8 + (size_t)m * N + nn) = cvt2_e4m3(v0, v1);
                } else {
                    *(__nv_bfloat162*)(outb + (size_t)m * N + nn) =
                        __nv_bfloat162(__float2bfloat16(v0), __float2bfloat16(v1));
                }
            }
        }
    }
}

// ============ fp8 fused residual GEMM (N=256): x += A@W^T+b ; x2=mod(ln(x)) =
#define GEMMRM_SMEM (3 * 49152)

template<int MOD>
__global__ void __launch_bounds__(512)
k_gemm_rm8(const fp8* __restrict__ A, const fp8* __restrict__ W,
           const float* __restrict__ bias, bf16* __restrict__ x,
           fp8* __restrict__ x2, const float* __restrict__ ssall,
           int off, int M, int K)
{
    extern __shared__ __align__(128) char smem[];
    const uint32_t sbase = (uint32_t)__cvta_generic_to_shared(smem);
    const int tid  = threadIdx.x;
    const int wid  = tid >> 5;
    const int lane = tid & 31;
    const int m0   = blockIdx.x * 128;
    const int wm   = (wid >> 2) * 32;
    const int wn   = (wid & 3) * 64;

    float acc[2][8][4];
    #pragma unroll
    for (int i = 0; i < 2; i++)
        #pragma unroll
        for (int j = 0; j < 8; j++)
            #pragma unroll
            for (int e = 0; e < 4; e++) acc[i][j][e] = 0.f;

    const int nk = K >> 7;

    auto stage_load = [&](int kt) {
        char* sA = smem + (kt % 3) * 49152;
        char* sB = sA + 16384;
        const fp8* gA = A + (size_t)m0 * K + kt * 128;
        const fp8* gB = W + (size_t)kt * 128;
        #pragma unroll
        for (int i = tid; i < 1024; i += 512) {
            int row = i >> 3, g = i & 7;
            cp16(sA + row * 128 + 16 * (g ^ (row & 7)), gA + (size_t)row * K + g * 16);
        }
        #pragma unroll
        for (int i = tid; i < 2048; i += 512) {
            int row = i >> 3, g = i & 7;
            cp16(sB + row * 128 + 16 * (g ^ (row & 7)), gB + (size_t)row * K + g * 16);
        }
        cp_commit();
    };

    stage_load(0);
    if (nk > 1) stage_load(1);

    const int aRow = (lane & 7) + (((lane >> 3) & 1) << 3);
    const int bRow = (lane & 7) + (((lane >> 4) & 1) << 3);
    const int l7   = lane & 7;

    for (int kt = 0; kt < nk; kt++) {
        if (kt < nk - 1) cp_wait<1>(); else cp_wait<0>();
        __syncthreads();
        if (kt + 2 < nk) stage_load(kt + 2);

        uint32_t sA = sbase + (uint32_t)(kt % 3) * 49152;
        uint32_t sB = sA + 16384;
        #pragma unroll
        for (int ks = 0; ks < 4; ks++) {
            uint32_t a[2][4], b[8][2];
            int ca = (ks * 2 + (lane >> 4)) ^ l7;
            int cb = (ks * 2 + ((lane >> 3) & 1)) ^ l7;
            #pragma unroll
            for (int i = 0; i < 2; i++)
                ldsm4(a[i][0], a[i][1], a[i][2], a[i][3],
                      sA + (uint32_t)(wm + i * 16 + aRow) * 128 + ca * 16);
            #pragma unroll
            for (int g = 0; g < 4; g++)
                ldsm4(b[g * 2][0], b[g * 2][1], b[g * 2 + 1][0], b[g * 2 + 1][1],
                      sB + (uint32_t)(wn + g * 16 + bRow) * 128 + cb * 16);
            #pragma unroll
            for (int i = 0; i < 2; i++)
                #pragma unroll
                for (int j = 0; j < 8; j++)
                    mma16832(acc[i][j], a[i], b[j]);
        }
    }

    __syncthreads();
    float* parts = (float*)smem;
    const int r = lane >> 2;
    const int c = (lane & 3) * 2;

    #pragma unroll
    for (int i = 0; i < 2; i++) {
        #pragma unroll
        for (int h = 0; h < 2; h++) {
            int ml = wm + i * 16 + r + h * 8;
            int m  = m0 + ml;
            float s = 0.f, q = 0.f;
            #pragma unroll
            for (int j = 0; j < 8; j++) {
                int nn = wn + j * 8 + c;
                __nv_bfloat162 xo = *(__nv_bfloat162*)(x + (size_t)m * 256 + nn);
                float v0 = acc[i][j][h * 2 + 0] * INV32 + bias[nn]     + __bfloat162float(xo.x);
                float v1 = acc[i][j][h * 2 + 1] * INV32 + bias[nn + 1] + __bfloat162float(xo.y);
                acc[i][j][h * 2 + 0] = v0;
                acc[i][j][h * 2 + 1] = v1;
                s += v0 + v1;
                q += v0 * v0 + v1 * v1;
                *(__nv_bfloat162*)(x + (size_t)m * 256 + nn) =
                    __nv_bfloat162(__float2bfloat16(v0), __float2bfloat16(v1));
            }
            if (MOD) {
                s += __shfl_xor_sync(0xffffffffu, s, 1);
                s += __shfl_xor_sync(0xffffffffu, s, 2);
                q += __shfl_xor_sync(0xffffffffu, q, 1);
                q += __shfl_xor_sync(0xffffffffu, q, 2);
                if ((lane & 3) == 0) {
                    parts[ml * 8 + (wid & 3) * 2 + 0] = s;
                    parts[ml * 8 + (wid & 3) * 2 + 1] = q;
                }
            }
        }
    }
    if (!MOD) return;
    __syncthreads();

    #pragma unroll
    for (int i = 0; i < 2; i++) {
        #pragma unroll
        for (int h = 0; h < 2; h++) {
            int ml = wm + i * 16 + r + h * 8;
            int m  = m0 + ml;
            float s = parts[ml * 8 + 0] + parts[ml * 8 + 2] + parts[ml * 8 + 4] + parts[ml * 8 + 6];
            float q = parts[ml * 8 + 1] + parts[ml * 8 + 3] + parts[ml * 8 + 5] + parts[ml * 8 + 7];
            float mean = s * (1.f / 256.f);
            float var  = q * (1.f / 256.f) - mean * mean;
            float rinv = rsqrtf(var + 1e-5f);
            const float* ssb = ssall + (size_t)(m / CT) * 6144 + off;
            #pragma unroll
            for (int j = 0; j < 8; j++) {
                int nn = wn + j * 8 + c;
                float xn0 = (acc[i][j][h * 2 + 0] - mean) * rinv;
                float xn1 = (acc[i][j][h * 2 + 1] - mean) * rinv;
                float o0 = (1.f + ssb[nn])     * xn0 + ssb[256 + nn];
                float o1 = (1.f + ssb[nn + 1]) * xn1 + ssb[256 + nn + 1];
                *(uint16_t*)(x2 + (size_t)m * 256 + nn) = cvt2_e4m3(o0, o1);
            }
        }
    }
}

// ============ ONE fused weight/input convert kernel =========================
#define N_CANVAS 3145728
#define N_CEW1   196608
#define N_CEW2   131072
#define N_FW2    262144
#define N_FW1    163840
#define N_ADW    1572864
#define N_ADB    6144
#define N_INP    1179648
#define N_OUTP   393216
#define N_FF1T   1572864
#define N_FF2T   1572864
#define N_WCONV  (N_CANVAS+N_CEW1+N_CEW2+N_FW2+N_FW1+N_ADW+N_ADB+N_INP+N_OUTP+N_FF1T+N_FF2T)

__global__ void k_wconv(const float* __restrict__ canvas, const float* __restrict__ cew1,
                        const float* __restrict__ cew2, const float* __restrict__ fw2,
                        const float* __restrict__ fw1,
                        const float* __restrict__ adw1, const float* __restrict__ adw2,
                        const float* __restrict__ adb1, const float* __restrict__ adb2,
                        const float* __restrict__ inp, const float* __restrict__ outp,
                        const float* __restrict__ ff1, const float* __restrict__ ff2,
                        bf16* d_canvas, bf16* d_cew1, bf16* d_cew2, bf16* d_fw2,
                        bf16* d_fw1, bf16* d_adw, float* d_adb,
                        fp8* d_inp, fp8* d_outp, fp8* d_ff1, fp8* d_ff2)
{
    int i = blockIdx.x * 256 + threadIdx.x;
    if (i < N_CANVAS) { d_canvas[i] = __float2bfloat16(canvas[i]); return; }
    i -= N_CANVAS;
    if (i < N_CEW1) { d_cew1[i] = __float2bfloat16(cew1[i]); return; }
    i -= N_CEW1;
    if (i < N_CEW2) { d_cew2[i] = __float2bfloat16(cew2[i]); return; }
    i -= N_CEW2;
    if (i < N_FW2) { d_fw2[i] = __float2bfloat16(fw2[i]); return; }
    i -= N_FW2;
    if (i < N_FW1) {
        int r = i / 320, k = i % 320;
        d_fw1[i] = (k < 296) ? __float2bfloat16(fw1[r * 296 + k]) : __float2bfloat16(0.f);
        return;
    }
    i -= N_FW1;
    if (i < N_ADW) {
        int row = i >> 8, k = i & 255;
        int l = row >> 10, r = row & 1023;
        float v = (r < 512) ? adw1[(size_t)l * 512 * 256 + r * 256 + k]
                            : adw2[(size_t)l * 512 * 256 + (r - 512) * 256 + k];
        d_adw[i] = __float2bfloat16(v);
        return;
    }
    i -= N_ADW;
    if (i < N_ADB) {
        int l = i >> 10, r = i & 1023;
        d_adb[i] = (r < 512) ? adb1[l * 512 + r] : adb2[l * 512 + (r - 512)];
        return;
    }
    i -= N_ADB;
    if (i < N_INP)  { d_inp[i]  = cvt1_e4m3(inp[i]  * 32.f); return; }
    i -= N_INP;
    if (i < N_OUTP) { d_outp[i] = cvt1_e4m3(outp[i] * 32.f); return; }
    i -= N_OUTP;
    if (i < N_FF1T) { d_ff1[i]  = cvt1_e4m3(ff1[i]  * 32.f); return; }
    i -= N_FF1T;
    if (i < N_FF2T) { d_ff2[i]  = cvt1_e4m3(ff2[i]  * 32.f); return; }
}

// ---------------- stroke embedding + layer-0 mod1 ----------------
__global__ void k_semb_mod(const float* __restrict__ strokes, const float* __restrict__ sp_w,
                           const float* __restrict__ sp_b, const float* __restrict__ pos,
                           const float* __restrict__ ssall,
                           bf16* __restrict__ x, fp8* __restrict__ x2)
{
    int row = blockIdx.x;
    int t = row % CT;
    int b = row / CT;
    __shared__ float st[8];
    __shared__ float red[2][8];
    __shared__ float stats[2];
    if (threadIdx.x < 8) st[threadIdx.x] = strokes[(size_t)row * 8 + threadIdx.x];
    __syncthreads();
    int d = threadIdx.x;
    float v = sp_b[d] + pos[t * CD + d];
    #pragma unroll
    for (int s = 0; s < 8; s++) v += st[s] * sp_w[d * 8 + s];
    x[(size_t)row * CD + d] = __float2bfloat16(v);

    float s = v, q = v * v;
    #pragma unroll
    for (int sh = 16; sh; sh >>= 1) {
        s += __shfl_xor_sync(0xffffffffu, s, sh);
        q += __shfl_xor_sync(0xffffffffu, q, sh);
    }
    if ((d & 31) == 0) { red[0][d >> 5] = s; red[1][d >> 5] = q; }
    __syncthreads();
    if (d == 0) {
        float a = 0.f, qq = 0.f;
        #pragma unroll
        for (int i = 0; i < 8; i++) { a += red[0][i]; qq += red[1][i]; }
        float mean = a * (1.f / 256.f);
        float var  = qq * (1.f / 256.f) - mean * mean;
        stats[0] = mean;
        stats[1] = rsqrtf(var + 1e-5f);
    }
    __syncthreads();
    const float* ssb = ssall + (size_t)b * 6144;
    float xn = (v - stats[0]) * stats[1];
    float o  = (1.f + ssb[d]) * xn + ssb[256 + d];
    float o_hi = __shfl_down_sync(0xffffffffu, o, 1);
    if (!(d & 1))
        *(uint16_t*)(x2 + (size_t)row * CD + d) = cvt2_e4m3(o, o_hi);
}

// ---------------- attention (o -> fp8) ----------------
__global__ void k_attn(const bf16* __restrict__ qkv, fp8* __restrict__ o8)
{
    int bh = blockIdx.x;
    int b = bh >> 3, h = bh & 7;
    __shared__ float sq[CT][33], sk[CT][33], sv[CT][33], sp[CT][33];
    int tid = threadIdx.x;
    size_t base = (size_t)b * CT * 768 + h * 32;
    for (int idx = tid; idx < CT * 32; idx += 128) {
        int t = idx >> 5, d = idx & 31;
        size_t p = base + (size_t)t * 768 + d;
        sq[t][d] = __bfloat162float(qkv[p]);
        sk[t][d] = __bfloat162float(qkv[p + 256]);
        sv[t][d] = __bfloat162float(qkv[p + 512]);
    }
    __syncthreads();
    const float scale = 0.17677669529663687f;
    for (int idx = tid; idx < CT * CT; idx += 128) {
        int i = idx / CT, j = idx % CT;
        if (j <= i) {
            float s = 0.f;
            #pragma unroll
            for (int d = 0; d < 32; d++) s += sq[i][d] * sk[j][d];
            sp[i][j] = s * scale;
        }
    }
    __syncthreads();
    int lane = tid & 31, w = tid >> 5;
    for (int i = w; i < CT; i += 4) {
        float v = (lane <= i) ? sp[i][lane] : -1e30f;
        float mx = v;
        #pragma unroll
        for (int s = 16; s; s >>= 1) mx = fmaxf(mx, __shfl_xor_sync(0xffffffffu, mx, s));
        float e = (lane <= i) ? __expf(v - mx) : 0.f;
        float sum = e;
        #pragma unroll
        for (int s = 16; s; s >>= 1) sum += __shfl_xor_sync(0xffffffffu, sum, s);
        if (lane <= i) sp[i][lane] = e / sum;
    }
    __syncthreads();
    for (int idx = tid; idx < CT * 16; idx += 128) {
        int i = idx >> 4, dp = (idx & 15) * 2;
        float s0 = 0.f, s1 = 0.f;
        for (int j = 0; j <= i; j++) {
            float p = sp[i][j];
            s0 += p * sv[j][dp];
            s1 += p * sv[j][dp + 1];
        }
        *(uint16_t*)(o8 + (size_t)(b * CT + i) * CD + h * 32 + dp) = cvt2_e4m3(s0, s1);
    }
}

// ---------------- final LN + flow-matching input ----------------
__global__ void k_final(const bf16* __restrict__ x, const float* __restrict__ on_g,
                        const float* __restrict__ on_b, const float* __restrict__ a_tar,
                        const float* __restrict__ a_src, const float* __restrict__ t,
                        bf16* __restrict__ xin)
{
    int b = blockIdx.x;
    const bf16* xr = x + ((size_t)b * CT + 29) * CD;
    __shared__ float rbuf[2][8];
    __shared__ float stats[2];
    int tid = threadIdx.x;
    float v = __bfloat162float(xr[tid]);
    float s = v, s2 = v * v;
    #pragma unroll
    for (int sh = 16; sh; sh >>= 1) {
        s  += __shfl_xor_sync(0xffffffffu, s, sh);
        s2 += __shfl_xor_sync(0xffffffffu, s2, sh);
    }
    if ((tid & 31) == 0) { rbuf[0][tid >> 5] = s; rbuf[1][tid >> 5] = s2; }
    __syncthreads();
    if (tid == 0) {
        float a = 0.f, q = 0.f;
        #pragma unroll
        for (int i = 0; i < 8; i++) { a += rbuf[0][i]; q += rbuf[1][i]; }
        float mean = a * (1.f / 256.f);
        float var  = q * (1.f / 256.f) - mean * mean;
        stats[0] = mean;
        stats[1] = rsqrtf(var + 1e-5f);
    }
    __syncthreads();
    float hn = (v - stats[0]) * stats[1] * on_g[tid] + on_b[tid];
    xin[(size_t)b * 320 + tid] = __float2bfloat16(hn);
    if (tid < 64) {
        int c = 256 + tid;
        float tv = t[b];
        float ov = 0.f;
        if (c < 264) {
            int i = c - 256;
            ov = (1.f - tv) * a_src[b * 8 + i] + tv * a_tar[b * 8 + i];
        } else if (c < 296) {
            int i = c - 264;
            int j = (i < 16) ? i : i - 16;
            float f = __expf(-9.210340371976184f * (float)j / 15.f);
            float a = tv * f;
            ov = (i < 16) ? sinf(a) : cosf(a);
        }
        xin[(size_t)b * 320 + c] = __float2bfloat16(ov);
    }
}

// ---------------- fm3 + loss ----------------
__global__ void k_fm3(const bf16* __restrict__ t2, const float* __restrict__ w3,
                      const float* __restrict__ b3, const float* __restrict__ a_tar,
                      const float* __restrict__ a_src, float* __restrict__ part)
{
    __shared__ float sw3[8 * 512];
    int tid = threadIdx.x;
    for (int i = tid; i < 8 * 512; i += 256) sw3[i] = w3[i];
    __syncthreads();
    int b = blockIdx.x * 256 + tid;
    float acc[8];
    #pragma unroll
    for (int o = 0; o < 8; o++) acc[o] = b3[o];
    const bf16* tr = t2 + (size_t)b * 512;
    for (int k = 0; k < 512; k++) {
        float tv = __bfloat162float(tr[k]);
        #pragma unroll
        for (int o = 0; o < 8; o++) acc[o] += tv * sw3[o * 512 + k];
    }
    float local = 0.f;
    #pragma unroll
    for (int o = 0; o < 8; o++) {
        float u = a_tar[b * 8 + o] - a_src[b * 8 + o];
        float d = acc[o] - u;
        local += d * d;
    }
    local *= (1.f / 65536.f);
    #pragma unroll
    for (int sh = 16; sh; sh >>= 1) local += __shfl_xor_sync(0xffffffffu, local, sh);
    __shared__ float rb[8];
    if ((tid & 31) == 0) rb[tid >> 5] = local;
    __syncthreads();
    if (tid == 0) {
        float s = 0.f;
        #pragma unroll
        for (int i = 0; i < 8; i++) s += rb[i];
        part[blockIdx.x] = s;
    }
}

__global__ void k_reduce(const float* __restrict__ part, float* __restrict__ out)
{
    float s = part[threadIdx.x];
    #pragma unroll
    for (int sh = 16; sh; sh >>= 1) s += __shfl_xor_sync(0xffffffffu, s, sh);
    if (threadIdx.x == 0) out[0] = s;
}

// ---------------- host side ------------------------------------------------
static void launch_gemm(int epi, const bf16* A, const bf16* W, const float* bias,
                        bf16* ob, float* of, int M, int N, int K)
{
    dim3 g(N / 128, M / 128);
    switch (epi) {
        case 0: k_gemm<0><<<g, 256, GEMM_SMEM>>>(A, W, bias, ob, of, M, N, K); break;
        case 1: k_gemm<1><<<g, 256, GEMM_SMEM>>>(A, W, bias, ob, of, M, N, K); break;
        default: k_gemm<3><<<g, 256, GEMM_SMEM>>>(A, W, bias, ob, of, M, N, K); break;
    }
}

#define GETSYM(var, sym) do { void* _p; cudaGetSymbolAddress(&_p, sym); var = (decltype(var))_p; } while (0)

extern "C" void kernel_launch(void* const* d_in, const int* in_sizes, int n_in,
                              void* d_out, int out_size)
{
    const float* strokes    = (const float*)d_in[0];
    const float* canvas     = (const float*)d_in[1];
    const float* a_tar      = (const float*)d_in[2];
    const float* a_src      = (const float*)d_in[3];
    const float* t_in       = (const float*)d_in[4];
    const float* ce_w1      = (const float*)d_in[5];
    const float* ce_b1      = (const float*)d_in[6];
    const float* ce_w2      = (const float*)d_in[7];
    const float* ce_b2      = (const float*)d_in[8];
    const float* sp_w       = (const float*)d_in[9];
    const float* sp_b       = (const float*)d_in[10];
    const float* pos_emb    = (const float*)d_in[11];
    const float* adaln1_w   = (const float*)d_in[12];
    const float* adaln1_b   = (const float*)d_in[13];
    const float* inproj_w   = (const float*)d_in[14];
    const float* inproj_b   = (const float*)d_in[15];
    const float* outproj_w  = (const float*)d_in[16];
    const float* outproj_b  = (const float*)d_in[17];
    const float* adaln2_w   = (const float*)d_in[18];
    const float* adaln2_b   = (const float*)d_in[19];
    const float* ff1_w      = (const float*)d_in[20];
    const float* ff1_b      = (const float*)d_in[21];
    const float* ff2_w      = (const float*)d_in[22];
    const float* ff2_b      = (const float*)d_in[23];
    const float* on_g       = (const float*)d_in[24];
    const float* on_b       = (const float*)d_in[25];
    const float* fm_w1      = (const float*)d_in[26];
    const float* fm_b1      = (const float*)d_in[27];
    const float* fm_w2      = (const float*)d_in[28];
    const float* fm_b2      = (const float*)d_in[29];
    const float* fm_w3      = (const float*)d_in[30];
    const float* fm_b3      = (const float*)d_in[31];
    float* out = (float*)d_out;
    (void)in_sizes; (void)n_in; (void)out_size;

    static int attr_done = 0;
    if (!attr_done) {
        cudaFuncSetAttribute(k_gemm<0>, cudaFuncAttributeMaxDynamicSharedMemorySize, GEMM_SMEM);
        cudaFuncSetAttribute(k_gemm<1>, cudaFuncAttributeMaxDynamicSharedMemorySize, GEMM_SMEM);
        cudaFuncSetAttribute(k_gemm<3>, cudaFuncAttributeMaxDynamicSharedMemorySize, GEMM_SMEM);
        cudaFuncSetAttribute(k_gemm8<0>, cudaFuncAttributeMaxDynamicSharedMemorySize, GEMM_SMEM);
        cudaFuncSetAttribute(k_gemm8<1>, cudaFuncAttributeMaxDynamicSharedMemorySize, GEMM_SMEM);
        cudaFuncSetAttribute(k_gemm_rm8<0>, cudaFuncAttributeMaxDynamicSharedMemorySize, GEMMRM_SMEM);
        cudaFuncSetAttribute(k_gemm_rm8<1>, cudaFuncAttributeMaxDynamicSharedMemorySize, GEMMRM_SMEM);
        attr_done = 1;
    }

    bf16 *p_canvas, *p_t1, *p_t2, *p_cv, *p_xb, *p_qkv, *p_xin;
    fp8  *p_x28, *p_o8, *p_ffh8, *p_inp8, *p_outp8, *p_ff18, *p_ff28;
    bf16 *p_cew1, *p_cew2, *p_adw, *p_fw1, *p_fw2;
    float *p_ssall, *p_adb, *p_part;
    GETSYM(p_canvas, g_canvas); GETSYM(p_t1, g_t1); GETSYM(p_t2, g_t2b);
    GETSYM(p_cv, g_cv); GETSYM(p_xb, g_xb); GETSYM(p_qkv, g_qkv); GETSYM(p_xin, g_xin);
    GETSYM(p_x28, g_x28); GETSYM(p_o8, g_o8); GETSYM(p_ffh8, g_ffh8);
    GETSYM(p_inp8, g_inp8); GETSYM(p_outp8, g_outp8); GETSYM(p_ff18, g_ff18);
    GETSYM(p_ff28, g_ff28);
    GETSYM(p_cew1, g_ce_w1); GETSYM(p_cew2, g_ce_w2);
    GETSYM(p_adw, g_adw); GETSYM(p_adb, g_adb);
    GETSYM(p_fw1, g_fw1); GETSYM(p_fw2, g_fw2);
    GETSYM(p_ssall, g_ssall); GETSYM(p_part, g_part);

    // [0] one fused convert kernel (everything)
    k_wconv<<<(N_WCONV + 255) / 256, 256>>>(
        canvas, ce_w1, ce_w2, fm_w2, fm_w1,
        adaln1_w, adaln2_w, adaln1_b, adaln2_b,
        inproj_w, outproj_w, ff1_w, ff2_w,
        p_canvas, p_cew1, p_cew2, p_fw2, p_fw1, p_adw, p_adb,
        p_inp8, p_outp8, p_ff18, p_ff28);

    const int M = CB * CT;

    // [1][2] context embedding ; [3] adaLN ; [4] semb+mod
    launch_gemm(1, p_canvas, p_cew1, ce_b1, p_t1, nullptr, CB, 512, 384);
    launch_gemm(0, p_t1,     p_cew2, ce_b2, p_cv, nullptr, CB, 256, 512);
    launch_gemm(3, p_cv, p_adw, p_adb, nullptr, p_ssall, CB, 6144, 256);
    k_semb_mod<<<M, 256>>>(strokes, sp_w, sp_b, pos_emb, p_ssall, p_xb, p_x28);

    for (int l = 0; l < CL; l++) {
        // [5 at l=0] qkv (fp8)  <- ncu profiles this
        k_gemm8<0><<<dim3(768 / 128, M / 128), 256, GEMM_SMEM>>>(
            p_x28, p_inp8 + (size_t)l * 768 * 256, inproj_b + l * 768,
            p_qkv, nullptr, M, 768, 256);
        k_attn<<<CB * 8, 128>>>(p_qkv, p_o8);
        // outproj: x += o@W^T + b ; x2 = mod2
        k_gemm_rm8<1><<<M / 128, 512, GEMMRM_SMEM>>>(
            p_o8, p_outp8 + (size_t)l * 256 * 256, outproj_b + l * 256,
            p_xb, p_x28, p_ssall, l * 1024 + 512, M, 256);
        // ff1 (fp8, silu -> fp8)
        k_gemm8<1><<<dim3(1024 / 128, M / 128), 256, GEMM_SMEM>>>(
            p_x28, p_ff18 + (size_t)l * 1024 * 256, ff1_b + l * 1024,
            nullptr, p_ffh8, M, 1024, 256);
        // ff2: x += ffh@W^T + b ; x2 = next mod1
        if (l < CL - 1) {
            k_gemm_rm8<1><<<M / 128, 512, GEMMRM_SMEM>>>(
                p_ffh8, p_ff28 + (size_t)l * 256 * 1024, ff2_b + l * 256,
                p_xb, p_x28, p_ssall, (l + 1) * 1024, M, 1024);
        } else {
            k_gemm_rm8<0><<<M / 128, 512, GEMMRM_SMEM>>>(
                p_ffh8, p_ff28 + (size_t)l * 256 * 1024, ff2_b + l * 256,
                p_xb, p_x28, p_ssall, 0, M, 1024);
        }
    }

    // final LN + flow-matching head (bf16)
    k_final<<<CB, 256>>>(p_xb, on_g, on_b, a_tar, a_src, t_in, p_xin);
    launch_gemm(1, p_xin, p_fw1, fm_b1, p_t1, nullptr, CB, 512, 320);
    launch_gemm(1, p_t1,  p_fw2, fm_b2, p_t2, nullptr, CB, 512, 512);
    k_fm3<<<32, 256>>>(p_t2, fm_w3, fm_b3, a_tar, a_src, p_part);
    k_reduce<<<1, 32>>>(p_part, out);
}

// round 14
// speedup vs baseline: 1.1971x; 1.1971x over previous
#include <cuda_runtime.h>
#include <cuda_bf16.h>
#include <cstdint>

typedef __nv_bfloat16 bf16;

#define CB 8192
#define CT 30
#define CD 256
#define CL 6

// ---------------- scratch ----------------
__device__ bf16  g_canvas[CB*384];
__device__ bf16  g_t1[CB*512];
__device__ bf16  g_t2b[CB*512];
__device__ bf16  g_cv[CB*256];
__device__ bf16  g_ssall[(size_t)CB*6144];   // bf16 adaLN scale/shift
__device__ bf16  g_xb[(size_t)CB*CT*CD];     // bf16 residual stream
__device__ bf16  g_x2[(size_t)CB*CT*CD];
__device__ bf16  g_qkv[(size_t)CB*CT*768];
__device__ bf16  g_ffh[(size_t)CB*CT*1024];
__device__ bf16  g_xin[CB*320];
__device__ float g_part[64];

__device__ bf16  g_ce_w1[512*384];
__device__ bf16  g_ce_w2[256*512];
__device__ bf16  g_adw[(size_t)6144*256];
__device__ float g_adb[6144];
__device__ bf16  g_inp[CL*768*256];
__device__ bf16  g_outp[CL*256*256];
__device__ bf16  g_ff1[CL*1024*256];
__device__ bf16  g_ff2[CL*256*1024];
__device__ bf16  g_fw1[512*320];
__device__ bf16  g_fw2[512*512];

// ---------------- asm helpers ----------------
__device__ __forceinline__ void cp16(void* smem, const void* gmem) {
    uint32_t s = (uint32_t)__cvta_generic_to_shared(smem);
    asm volatile("cp.async.cg.shared.global [%0], [%1], 16;\n" :: "r"(s), "l"(gmem));
}
__device__ __forceinline__ void cp_commit() { asm volatile("cp.async.commit_group;\n"); }
template<int N> __device__ __forceinline__ void cp_wait() {
    asm volatile("cp.async.wait_group %0;\n" :: "n"(N));
}
__device__ __forceinline__ void ldsm4(uint32_t& r0, uint32_t& r1, uint32_t& r2, uint32_t& r3,
                                      uint32_t addr) {
    asm volatile("ldmatrix.sync.aligned.m8n8.x4.shared.b16 {%0,%1,%2,%3}, [%4];"
                 : "=r"(r0), "=r"(r1), "=r"(r2), "=r"(r3) : "r"(addr));
}
__device__ __forceinline__ void mma16816(float* d, const uint32_t* a, const uint32_t* b) {
    asm volatile("mma.sync.aligned.m16n8k16.row.col.f32.bf16.bf16.f32 "
                 "{%0,%1,%2,%3}, {%4,%5,%6,%7}, {%8,%9}, {%0,%1,%2,%3};"
                 : "+f"(d[0]), "+f"(d[1]), "+f"(d[2]), "+f"(d[3])
                 : "r"(a[0]), "r"(a[1]), "r"(a[2]), "r"(a[3]), "r"(b[0]), "r"(b[1]));
}

// ============ bf16 GEMM (BN=128, BK=64), double-buffered fragments =========
// EPI: 0 bias->bf16 ; 1 bias+silu->bf16
#define GEMM_SMEM (3 * 32768)

template<int EPI>
__global__ void __launch_bounds__(256)
k_gemm(const bf16* __restrict__ A, const bf16* __restrict__ W,
       const float* __restrict__ bias, bf16* __restrict__ outb,
       int M, int N, int K)
{
    extern __shared__ __align__(128) char smem[];
    const uint32_t sbase = (uint32_t)__cvta_generic_to_shared(smem);
    const int tid  = threadIdx.x;
    const int wid  = tid >> 5;
    const int lane = tid & 31;
    const int n0   = blockIdx.x * 128;
    const int m0   = blockIdx.y * 128;
    const int wm   = (wid >> 2) * 64;
    const int wn   = (wid & 3) * 32;

    float acc[4][4][4];
    #pragma unroll
    for (int i = 0; i < 4; i++)
        #pragma unroll
        for (int j = 0; j < 4; j++)
            #pragma unroll
            for (int e = 0; e < 4; e++) acc[i][j][e] = 0.f;

    const int nk = K >> 6;

    auto stage_load = [&](int kt) {
        char* sA = smem + (kt % 3) * 32768;
        char* sB = sA + 16384;
        const bf16* gA = A + (size_t)m0 * K + kt * 64;
        const bf16* gB = W + (size_t)n0 * K + kt * 64;
        #pragma unroll
        for (int i = tid; i < 1024; i += 256) {
            int row = i >> 3, g = i & 7;
            cp16(sA + row * 128 + 16 * (g ^ (row & 7)), gA + (size_t)row * K + g * 8);
        }
        #pragma unroll
        for (int i = tid; i < 1024; i += 256) {
            int row = i >> 3, g = i & 7;
            cp16(sB + row * 128 + 16 * (g ^ (row & 7)), gB + (size_t)row * K + g * 8);
        }
        cp_commit();
    };

    stage_load(0);
    if (nk > 1) stage_load(1);

    const int aRow = (lane & 7) + (((lane >> 3) & 1) << 3);
    const int bRow = (lane & 7) + (((lane >> 4) & 1) << 3);
    const int l7   = lane & 7;

    for (int kt = 0; kt < nk; kt++) {
        if (kt < nk - 1) cp_wait<1>(); else cp_wait<0>();
        __syncthreads();
        if (kt + 2 < nk) stage_load(kt + 2);

        uint32_t sA = sbase + (uint32_t)(kt % 3) * 32768;
        uint32_t sB = sA + 16384;

        uint32_t a[2][4][4], b[2][4][2];
        auto frag_load = [&](int ks, int buf) {
            int ca = (ks * 2 + (lane >> 4)) ^ l7;
            int cb = (ks * 2 + ((lane >> 3) & 1)) ^ l7;
            #pragma unroll
            for (int i = 0; i < 4; i++)
                ldsm4(a[buf][i][0], a[buf][i][1], a[buf][i][2], a[buf][i][3],
                      sA + (uint32_t)(wm + i * 16 + aRow) * 128 + ca * 16);
            #pragma unroll
            for (int j2 = 0; j2 < 2; j2++)
                ldsm4(b[buf][j2 * 2][0], b[buf][j2 * 2][1],
                      b[buf][j2 * 2 + 1][0], b[buf][j2 * 2 + 1][1],
                      sB + (uint32_t)(wn + j2 * 16 + bRow) * 128 + cb * 16);
        };

        frag_load(0, 0);
        #pragma unroll
        for (int ks = 0; ks < 4; ks++) {
            int cur = ks & 1;
            if (ks < 3) frag_load(ks + 1, cur ^ 1);
            #pragma unroll
            for (int i = 0; i < 4; i++)
                #pragma unroll
                for (int j = 0; j < 4; j++)
                    mma16816(acc[i][j], a[cur][i], b[cur][j]);
        }
    }

    const int r = lane >> 2;
    const int c = (lane & 3) * 2;
    #pragma unroll
    for (int i = 0; i < 4; i++) {
        #pragma unroll
        for (int j = 0; j < 4; j++) {
            #pragma unroll
            for (int h = 0; h < 2; h++) {
                int m  = m0 + wm + i * 16 + r + h * 8;
                int nn = n0 + wn + j * 8 + c;
                float v0 = acc[i][j][h * 2 + 0] + bias[nn];
                float v1 = acc[i][j][h * 2 + 1] + bias[nn + 1];
                if (EPI == 1) {
                    v0 = v0 / (1.f + __expf(-v0));
                    v1 = v1 / (1.f + __expf(-v1));
                }
                *(__nv_bfloat162*)(outb + (size_t)m * N + nn) =
                    __nv_bfloat162(__float2bfloat16(v0), __float2bfloat16(v1));
            }
        }
    }
}

// ============ fused residual GEMM (N=256): x += A@W^T + b; x2 = mod(ln(x)) ==
#define GEMMRM_SMEM (3 * 49152)

template<int MOD>
__global__ void __launch_bounds__(512)
k_gemm_rm(const bf16* __restrict__ A, const bf16* __restrict__ W,
          const float* __restrict__ bias, bf16* __restrict__ x,
          bf16* __restrict__ x2, const bf16* __restrict__ ssall,
          int off, int M, int K)
{
    extern __shared__ __align__(128) char smem[];
    const uint32_t sbase = (uint32_t)__cvta_generic_to_shared(smem);
    const int tid  = threadIdx.x;
    const int wid  = tid >> 5;
    const int lane = tid & 31;
    const int m0   = blockIdx.x * 128;
    const int wm   = (wid >> 2) * 32;
    const int wn   = (wid & 3) * 64;

    float acc[2][8][4];
    #pragma unroll
    for (int i = 0; i < 2; i++)
        #pragma unroll
        for (int j = 0; j < 8; j++)
            #pragma unroll
            for (int e = 0; e < 4; e++) acc[i][j][e] = 0.f;

    const int nk = K >> 6;

    auto stage_load = [&](int kt) {
        char* sA = smem + (kt % 3) * 49152;
        char* sB = sA + 16384;
        const bf16* gA = A + (size_t)m0 * K + kt * 64;
        const bf16* gB = W + (size_t)kt * 64;
        #pragma unroll
        for (int i = tid; i < 1024; i += 512) {
            int row = i >> 3, g = i & 7;
            cp16(sA + row * 128 + 16 * (g ^ (row & 7)), gA + (size_t)row * K + g * 8);
        }
        #pragma unroll
        for (int i = tid; i < 2048; i += 512) {
            int row = i >> 3, g = i & 7;
            cp16(sB + row * 128 + 16 * (g ^ (row & 7)), gB + (size_t)row * K + g * 8);
        }
        cp_commit();
    };

    stage_load(0);
    if (nk > 1) stage_load(1);

    const int aRow = (lane & 7) + (((lane >> 3) & 1) << 3);
    const int bRow = (lane & 7) + (((lane >> 4) & 1) << 3);
    const int l7   = lane & 7;

    for (int kt = 0; kt < nk; kt++) {
        if (kt < nk - 1) cp_wait<1>(); else cp_wait<0>();
        __syncthreads();
        if (kt + 2 < nk) stage_load(kt + 2);

        uint32_t sA = sbase + (uint32_t)(kt % 3) * 49152;
        uint32_t sB = sA + 16384;
        #pragma unroll
        for (int ks = 0; ks < 4; ks++) {
            uint32_t a[2][4], b[8][2];
            int ca = (ks * 2 + (lane >> 4)) ^ l7;
            int cb = (ks * 2 + ((lane >> 3) & 1)) ^ l7;
            #pragma unroll
            for (int i = 0; i < 2; i++)
                ldsm4(a[i][0], a[i][1], a[i][2], a[i][3],
                      sA + (uint32_t)(wm + i * 16 + aRow) * 128 + ca * 16);
            #pragma unroll
            for (int g = 0; g < 4; g++)
                ldsm4(b[g * 2][0], b[g * 2][1], b[g * 2 + 1][0], b[g * 2 + 1][1],
                      sB + (uint32_t)(wn + g * 16 + bRow) * 128 + cb * 16);
            #pragma unroll
            for (int i = 0; i < 2; i++)
                #pragma unroll
                for (int j = 0; j < 8; j++)
                    mma16816(acc[i][j], a[i], b[j]);
        }
    }

    __syncthreads();
    float* parts = (float*)smem;
    const int r = lane >> 2;
    const int c = (lane & 3) * 2;

    #pragma unroll
    for (int i = 0; i < 2; i++) {
        #pragma unroll
        for (int h = 0; h < 2; h++) {
            int ml = wm + i * 16 + r + h * 8;
            int m  = m0 + ml;
            float s = 0.f, q = 0.f;
            #pragma unroll
            for (int j = 0; j < 8; j++) {
                int nn = wn + j * 8 + c;
                __nv_bfloat162 xo = *(__nv_bfloat162*)(x + (size_t)m * 256 + nn);
                float v0 = acc[i][j][h * 2 + 0] + bias[nn]     + __bfloat162float(xo.x);
                float v1 = acc[i][j][h * 2 + 1] + bias[nn + 1] + __bfloat162float(xo.y);
                acc[i][j][h * 2 + 0] = v0;
                acc[i][j][h * 2 + 1] = v1;
                s += v0 + v1;
                q += v0 * v0 + v1 * v1;
                *(__nv_bfloat162*)(x + (size_t)m * 256 + nn) =
                    __nv_bfloat162(__float2bfloat16(v0), __float2bfloat16(v1));
            }
            if (MOD) {
                s += __shfl_xor_sync(0xffffffffu, s, 1);
                s += __shfl_xor_sync(0xffffffffu, s, 2);
                q += __shfl_xor_sync(0xffffffffu, q, 1);
                q += __shfl_xor_sync(0xffffffffu, q, 2);
                if ((lane & 3) == 0) {
                    parts[ml * 8 + (wid & 3) * 2 + 0] = s;
                    parts[ml * 8 + (wid & 3) * 2 + 1] = q;
                }
            }
        }
    }
    if (!MOD) return;
    __syncthreads();

    #pragma unroll
    for (int i = 0; i < 2; i++) {
        #pragma unroll
        for (int h = 0; h < 2; h++) {
            int ml = wm + i * 16 + r + h * 8;
            int m  = m0 + ml;
            float s = parts[ml * 8 + 0] + parts[ml * 8 + 2] + parts[ml * 8 + 4] + parts[ml * 8 + 6];
            float q = parts[ml * 8 + 1] + parts[ml * 8 + 3] + parts[ml * 8 + 5] + parts[ml * 8 + 7];
            float mean = s * (1.f / 256.f);
            float var  = q * (1.f / 256.f) - mean * mean;
            float rinv = rsqrtf(var + 1e-5f);
            const bf16* ssb = ssall + (size_t)(m / CT) * 6144 + off;
            #pragma unroll
            for (int j = 0; j < 8; j++) {
                int nn = wn + j * 8 + c;
                __nv_bfloat162 sc = *(const __nv_bfloat162*)(ssb + nn);
                __nv_bfloat162 sh = *(const __nv_bfloat162*)(ssb + 256 + nn);
                float xn0 = (acc[i][j][h * 2 + 0] - mean) * rinv;
                float xn1 = (acc[i][j][h * 2 + 1] - mean) * rinv;
                float o0 = (1.f + __bfloat162float(sc.x)) * xn0 + __bfloat162float(sh.x);
                float o1 = (1.f + __bfloat162float(sc.y)) * xn1 + __bfloat162float(sh.y);
                *(__nv_bfloat162*)(x2 + (size_t)m * 256 + nn) =
                    __nv_bfloat162(__float2bfloat16(o0), __float2bfloat16(o1));
            }
        }
    }
}

// ============ ONE fused weight/input convert kernel =========================
#define N_CANVAS 3145728
#define N_CEW1   196608
#define N_CEW2   131072
#define N_FW2    262144
#define N_FW1    163840
#define N_ADW    1572864
#define N_ADB    6144
#define N_INP    1179648
#define N_OUTP   393216
#define N_FF1T   1572864
#define N_FF2T   1572864
#define N_WCONV  (N_CANVAS+N_CEW1+N_CEW2+N_FW2+N_FW1+N_ADW+N_ADB+N_INP+N_OUTP+N_FF1T+N_FF2T)

__global__ void k_wconv(const float* __restrict__ canvas, const float* __restrict__ cew1,
                        const float* __restrict__ cew2, const float* __restrict__ fw2,
                        const float* __restrict__ fw1,
                        const float* __restrict__ adw1, const float* __restrict__ adw2,
                        const float* __restrict__ adb1, const float* __restrict__ adb2,
                        const float* __restrict__ inp, const float* __restrict__ outp,
                        const float* __restrict__ ff1, const float* __restrict__ ff2,
                        bf16* d_canvas, bf16* d_cew1, bf16* d_cew2, bf16* d_fw2,
                        bf16* d_fw1, bf16* d_adw, float* d_adb,
                        bf16* d_inp, bf16* d_outp, bf16* d_ff1, bf16* d_ff2)
{
    int i = blockIdx.x * 256 + threadIdx.x;
    if (i < N_CANVAS) { d_canvas[i] = __float2bfloat16(canvas[i]); return; }
    i -= N_CANVAS;
    if (i < N_CEW1) { d_cew1[i] = __float2bfloat16(cew1[i]); return; }
    i -= N_CEW1;
    if (i < N_CEW2) { d_cew2[i] = __float2bfloat16(cew2[i]); return; }
    i -= N_CEW2;
    if (i < N_FW2) { d_fw2[i] = __float2bfloat16(fw2[i]); return; }
    i -= N_FW2;
    if (i < N_FW1) {
        int r = i / 320, k = i % 320;
        d_fw1[i] = (k < 296) ? __float2bfloat16(fw1[r * 296 + k]) : __float2bfloat16(0.f);
        return;
    }
    i -= N_FW1;
    if (i < N_ADW) {
        int row = i >> 8, k = i & 255;
        int l = row >> 10, r = row & 1023;
        float v = (r < 512) ? adw1[(size_t)l * 512 * 256 + r * 256 + k]
                            : adw2[(size_t)l * 512 * 256 + (r - 512) * 256 + k];
        d_adw[i] = __float2bfloat16(v);
        return;
    }
    i -= N_ADW;
    if (i < N_ADB) {
        int l = i >> 10, r = i & 1023;
        d_adb[i] = (r < 512) ? adb1[l * 512 + r] : adb2[l * 512 + (r - 512)];
        return;
    }
    i -= N_ADB;
    if (i < N_INP)  { d_inp[i]  = __float2bfloat16(inp[i]);  return; }
    i -= N_INP;
    if (i < N_OUTP) { d_outp[i] = __float2bfloat16(outp[i]); return; }
    i -= N_OUTP;
    if (i < N_FF1T) { d_ff1[i]  = __float2bfloat16(ff1[i]);  return; }
    i -= N_FF1T;
    if (i < N_FF2T) { d_ff2[i]  = __float2bfloat16(ff2[i]);  return; }
}

// ---------------- stroke embedding + layer-0 mod1 ----------------
__global__ void k_semb_mod(const float* __restrict__ strokes, const float* __restrict__ sp_w,
                           const float* __restrict__ sp_b, const float* __restrict__ pos,
                           const bf16* __restrict__ ssall,
                           bf16* __restrict__ x, bf16* __restrict__ x2)
{
    int row = blockIdx.x;
    int t = row % CT;
    int b = row / CT;
    __shared__ float st[8];
    __shared__ float red[2][8];
    __shared__ float stats[2];
    if (threadIdx.x < 8) st[threadIdx.x] = strokes[(size_t)row * 8 + threadIdx.x];
    __syncthreads();
    int d = threadIdx.x;
    float v = sp_b[d] + pos[t * CD + d];
    #pragma unroll
    for (int s = 0; s < 8; s++) v += st[s] * sp_w[d * 8 + s];
    x[(size_t)row * CD + d] = __float2bfloat16(v);

    float s = v, q = v * v;
    #pragma unroll
    for (int sh = 16; sh; sh >>= 1) {
        s += __shfl_xor_sync(0xffffffffu, s, sh);
        q += __shfl_xor_sync(0xffffffffu, q, sh);
    }
    if ((d & 31) == 0) { red[0][d >> 5] = s; red[1][d >> 5] = q; }
    __syncthreads();
    if (d == 0) {
        float a = 0.f, qq = 0.f;
        #pragma unroll
        for (int i = 0; i < 8; i++) { a += red[0][i]; qq += red[1][i]; }
        float mean = a * (1.f / 256.f);
        float var  = qq * (1.f / 256.f) - mean * mean;
        stats[0] = mean;
        stats[1] = rsqrtf(var + 1e-5f);
    }
    __syncthreads();
    const bf16* ssb = ssall + (size_t)b * 6144;
    float xn = (v - stats[0]) * stats[1];
    float o  = (1.f + __bfloat162float(ssb[d])) * xn + __bfloat162float(ssb[256 + d]);
    x2[(size_t)row * CD + d] = __float2bfloat16(o);
}

// ---------------- attention ----------------
__global__ void k_attn(const bf16* __restrict__ qkv, bf16* __restrict__ o)
{
    int bh = blockIdx.x;
    int b = bh >> 3, h = bh & 7;
    __shared__ float sq[CT][33], sk[CT][33], sv[CT][33], sp[CT][33];
    int tid = threadIdx.x;
    size_t base = (size_t)b * CT * 768 + h * 32;
    for (int idx = tid; idx < CT * 32; idx += 128) {
        int t = idx >> 5, d = idx & 31;
        size_t p = base + (size_t)t * 768 + d;
        sq[t][d] = __bfloat162float(qkv[p]);
        sk[t][d] = __bfloat162float(qkv[p + 256]);
        sv[t][d] = __bfloat162float(qkv[p + 512]);
    }
    __syncthreads();
    const float scale = 0.17677669529663687f;
    for (int idx = tid; idx < CT * CT; idx += 128) {
        int i = idx / CT, j = idx % CT;
        if (j <= i) {
            float s = 0.f;
            #pragma unroll
            for (int d = 0; d < 32; d++) s += sq[i][d] * sk[j][d];
            sp[i][j] = s * scale;
        }
    }
    __syncthreads();
    int lane = tid & 31, w = tid >> 5;
    for (int i = w; i < CT; i += 4) {
        float v = (lane <= i) ? sp[i][lane] : -1e30f;
        float mx = v;
        #pragma unroll
        for (int s = 16; s; s >>= 1) mx = fmaxf(mx, __shfl_xor_sync(0xffffffffu, mx, s));
        float e = (lane <= i) ? __expf(v - mx) : 0.f;
        float sum = e;
        #pragma unroll
        for (int s = 16; s; s >>= 1) sum += __shfl_xor_sync(0xffffffffu, sum, s);
        if (lane <= i) sp[i][lane] = e / sum;
    }
    __syncthreads();
    for (int idx = tid; idx < CT * 32; idx += 128) {
        int i = idx >> 5, d = idx & 31;
        float s = 0.f;
        for (int j = 0; j <= i; j++) s += sp[i][j] * sv[j][d];
        o[(size_t)(b * CT + i) * CD + h * 32 + d] = __float2bfloat16(s);
    }
}

// ---------------- final LN + flow-matching input ----------------
__global__ void k_final(const bf16* __restrict__ x, const float* __restrict__ on_g,
                        const float* __restrict__ on_b, const float* __restrict__ a_tar,
                        const float* __restrict__ a_src, const float* __restrict__ t,
                        bf16* __restrict__ xin)
{
    int b = blockIdx.x;
    const bf16* xr = x + ((size_t)b * CT + 29) * CD;
    __shared__ float rbuf[2][8];
    __shared__ float stats[2];
    int tid = threadIdx.x;
    float v = __bfloat162float(xr[tid]);
    float s = v, s2 = v * v;
    #pragma unroll
    for (int sh = 16; sh; sh >>= 1) {
        s  += __shfl_xor_sync(0xffffffffu, s, sh);
        s2 += __shfl_xor_sync(0xffffffffu, s2, sh);
    }
    if ((tid & 31) == 0) { rbuf[0][tid >> 5] = s; rbuf[1][tid >> 5] = s2; }
    __syncthreads();
    if (tid == 0) {
        float a = 0.f, q = 0.f;
        #pragma unroll
        for (int i = 0; i < 8; i++) { a += rbuf[0][i]; q += rbuf[1][i]; }
        float mean = a * (1.f / 256.f);
        float var  = q * (1.f / 256.f) - mean * mean;
        stats[0] = mean;
        stats[1] = rsqrtf(var + 1e-5f);
    }
    __syncthreads();
    float hn = (v - stats[0]) * stats[1] * on_g[tid] + on_b[tid];
    xin[(size_t)b * 320 + tid] = __float2bfloat16(hn);
    if (tid < 64) {
        int c = 256 + tid;
        float tv = t[b];
        float ov = 0.f;
        if (c < 264) {
            int i = c - 256;
            ov = (1.f - tv) * a_src[b * 8 + i] + tv * a_tar[b * 8 + i];
        } else if (c < 296) {
            int i = c - 264;
            int j = (i < 16) ? i : i - 16;
            float f = __expf(-9.210340371976184f * (float)j / 15.f);
            float a = tv * f;
            ov = (i < 16) ? sinf(a) : cosf(a);
        }
        xin[(size_t)b * 320 + c] = __float2bfloat16(ov);
    }
}

// ---------------- fm3 + loss ----------------
__global__ void k_fm3(const bf16* __restrict__ t2, const float* __restrict__ w3,
                      const float* __restrict__ b3, const float* __restrict__ a_tar,
                      const float* __restrict__ a_src, float* __restrict__ part)
{
    __shared__ float sw3[8 * 512];
    int tid = threadIdx.x;
    for (int i = tid; i < 8 * 512; i += 256) sw3[i] = w3[i];
    __syncthreads();
    int b = blockIdx.x * 256 + tid;
    float acc[8];
    #pragma unroll
    for (int o = 0; o < 8; o++) acc[o] = b3[o];
    const bf16* tr = t2 + (size_t)b * 512;
    for (int k = 0; k < 512; k++) {
        float tv = __bfloat162float(tr[k]);
        #pragma unroll
        for (int o = 0; o < 8; o++) acc[o] += tv * sw3[o * 512 + k];
    }
    float local = 0.f;
    #pragma unroll
    for (int o = 0; o < 8; o++) {
        float u = a_tar[b * 8 + o] - a_src[b * 8 + o];
        float d = acc[o] - u;
        local += d * d;
    }
    local *= (1.f / 65536.f);
    #pragma unroll
    for (int sh = 16; sh; sh >>= 1) local += __shfl_xor_sync(0xffffffffu, local, sh);
    __shared__ float rb[8];
    if ((tid & 31) == 0) rb[tid >> 5] = local;
    __syncthreads();
    if (tid == 0) {
        float s = 0.f;
        #pragma unroll
        for (int i = 0; i < 8; i++) s += rb[i];
        part[blockIdx.x] = s;
    }
}

__global__ void k_reduce(const float* __restrict__ part, float* __restrict__ out)
{
    float s = part[threadIdx.x];
    #pragma unroll
    for (int sh = 16; sh; sh >>= 1) s += __shfl_xor_sync(0xffffffffu, s, sh);
    if (threadIdx.x == 0) out[0] = s;
}

// ---------------- host side ------------------------------------------------
static void launch_gemm(int epi, const bf16* A, const bf16* W, const float* bias,
                        bf16* ob, int M, int N, int K)
{
    dim3 g(N / 128, M / 128);
    switch (epi) {
        case 0: k_gemm<0><<<g, 256, GEMM_SMEM>>>(A, W, bias, ob, M, N, K); break;
        default: k_gemm<1><<<g, 256, GEMM_SMEM>>>(A, W, bias, ob, M, N, K); break;
    }
}

#define GETSYM(var, sym) do { void* _p; cudaGetSymbolAddress(&_p, sym); var = (decltype(var))_p; } while (0)

extern "C" void kernel_launch(void* const* d_in, const int* in_sizes, int n_in,
                              void* d_out, int out_size)
{
    const float* strokes    = (const float*)d_in[0];
    const float* canvas     = (const float*)d_in[1];
    const float* a_tar      = (const float*)d_in[2];
    const float* a_src      = (const float*)d_in[3];
    const float* t_in       = (const float*)d_in[4];
    const float* ce_w1      = (const float*)d_in[5];
    const float* ce_b1      = (const float*)d_in[6];
    const float* ce_w2      = (const float*)d_in[7];
    const float* ce_b2      = (const float*)d_in[8];
    const float* sp_w       = (const float*)d_in[9];
    const float* sp_b       = (const float*)d_in[10];
    const float* pos_emb    = (const float*)d_in[11];
    const float* adaln1_w   = (const float*)d_in[12];
    const float* adaln1_b   = (const float*)d_in[13];
    const float* inproj_w   = (const float*)d_in[14];
    const float* inproj_b   = (const float*)d_in[15];
    const float* outproj_w  = (const float*)d_in[16];
    const float* outproj_b  = (const float*)d_in[17];
    const float* adaln2_w   = (const float*)d_in[18];
    const float* adaln2_b   = (const float*)d_in[19];
    const float* ff1_w      = (const float*)d_in[20];
    const float* ff1_b      = (const float*)d_in[21];
    const float* ff2_w      = (const float*)d_in[22];
    const float* ff2_b      = (const float*)d_in[23];
    const float* on_g       = (const float*)d_in[24];
    const float* on_b       = (const float*)d_in[25];
    const float* fm_w1      = (const float*)d_in[26];
    const float* fm_b1      = (const float*)d_in[27];
    const float* fm_w2      = (const float*)d_in[28];
    const float* fm_b2      = (const float*)d_in[29];
    const float* fm_w3      = (const float*)d_in[30];
    const float* fm_b3      = (const float*)d_in[31];
    float* out = (float*)d_out;
    (void)in_sizes; (void)n_in; (void)out_size;

    static int attr_done = 0;
    if (!attr_done) {
        cudaFuncSetAttribute(k_gemm<0>, cudaFuncAttributeMaxDynamicSharedMemorySize, GEMM_SMEM);
        cudaFuncSetAttribute(k_gemm<1>, cudaFuncAttributeMaxDynamicSharedMemorySize, GEMM_SMEM);
        cudaFuncSetAttribute(k_gemm_rm<0>, cudaFuncAttributeMaxDynamicSharedMemorySize, GEMMRM_SMEM);
        cudaFuncSetAttribute(k_gemm_rm<1>, cudaFuncAttributeMaxDynamicSharedMemorySize, GEMMRM_SMEM);
        attr_done = 1;
    }

    bf16 *p_canvas, *p_t1, *p_t2, *p_cv, *p_xb, *p_x2, *p_qkv, *p_ffh, *p_xin, *p_ssall;
    bf16 *p_cew1, *p_cew2, *p_adw, *p_inp, *p_outp, *p_ff1, *p_ff2, *p_fw1, *p_fw2;
    float *p_adb, *p_part;
    GETSYM(p_canvas, g_canvas); GETSYM(p_t1, g_t1); GETSYM(p_t2, g_t2b);
    GETSYM(p_cv, g_cv); GETSYM(p_xb, g_xb); GETSYM(p_x2, g_x2); GETSYM(p_qkv, g_qkv);
    GETSYM(p_ffh, g_ffh); GETSYM(p_xin, g_xin); GETSYM(p_ssall, g_ssall);
    GETSYM(p_cew1, g_ce_w1); GETSYM(p_cew2, g_ce_w2);
    GETSYM(p_adw, g_adw); GETSYM(p_adb, g_adb);
    GETSYM(p_inp, g_inp); GETSYM(p_outp, g_outp);
    GETSYM(p_ff1, g_ff1); GETSYM(p_ff2, g_ff2); GETSYM(p_fw1, g_fw1); GETSYM(p_fw2, g_fw2);
    GETSYM(p_part, g_part);

    // [0] one fused convert kernel
    k_wconv<<<(N_WCONV + 255) / 256, 256>>>(
        canvas, ce_w1, ce_w2, fm_w2, fm_w1,
        adaln1_w, adaln2_w, adaln1_b, adaln2_b,
        inproj_w, outproj_w, ff1_w, ff2_w,
        p_canvas, p_cew1, p_cew2, p_fw2, p_fw1, p_adw, p_adb,
        p_inp, p_outp, p_ff1, p_ff2);

    const int M = CB * CT;

    // context embedding ; adaLN (bf16 ssall) ; semb+mod
    launch_gemm(1, p_canvas, p_cew1, ce_b1, p_t1, CB, 512, 384);
    launch_gemm(0, p_t1,     p_cew2, ce_b2, p_cv, CB, 256, 512);
    launch_gemm(0, p_cv, p_adw, p_adb, p_ssall, CB, 6144, 256);
    k_semb_mod<<<M, 256>>>(strokes, sp_w, sp_b, pos_emb, p_ssall, p_xb, p_x2);

    for (int l = 0; l < CL; l++) {
        // [5 at l=0] qkv  <- ncu profiles this
        launch_gemm(0, p_x2, p_inp + (size_t)l * 768 * 256, inproj_b + l * 768,
                    p_qkv, M, 768, 256);
        k_attn<<<CB * 8, 128>>>(p_qkv, p_x2);
        k_gemm_rm<1><<<M / 128, 512, GEMMRM_SMEM>>>(
            p_x2, p_outp + (size_t)l * 256 * 256, outproj_b + l * 256,
            p_xb, p_x2, p_ssall, l * 1024 + 512, M, 256);
        launch_gemm(1, p_x2, p_ff1 + (size_t)l * 1024 * 256, ff1_b + l * 1024,
                    p_ffh, M, 1024, 256);
        if (l < CL - 1) {
            k_gemm_rm<1><<<M / 128, 512, GEMMRM_SMEM>>>(
                p_ffh, p_ff2 + (size_t)l * 256 * 1024, ff2_b + l * 256,
                p_xb, p_x2, p_ssall, (l + 1) * 1024, M, 1024);
        } else {
            k_gemm_rm<0><<<M / 128, 512, GEMMRM_SMEM>>>(
                p_ffh, p_ff2 + (size_t)l * 256 * 1024, ff2_b + l * 256,
                p_xb, p_x2, p_ssall, 0, M, 1024);
        }
    }

    // final LN + flow-matching head
    k_final<<<CB, 256>>>(p_xb, on_g, on_b, a_tar, a_src, t_in, p_xin);
    launch_gemm(1, p_xin, p_fw1, fm_b1, p_t1, CB, 512, 320);
    launch_gemm(1, p_t1,  p_fw2, fm_b2, p_t2, CB, 512, 512);
    k_fm3<<<32, 256>>>(p_t2, fm_w3, fm_b3, a_tar, a_src, p_part);
    k_reduce<<<1, 32>>>(p_part, out);
}